// round 6
// baseline (speedup 1.0000x reference)
#include <cuda_runtime.h>

#define B_ 2
#define N_ 16384
#define S_ 4096
#define K_ 32
#define C0 67
#define C1 64
#define C2 64
#define C3 128
#define FULLM 0xffffffffu
#define FINF 3.402823466e38f

typedef unsigned long long ull;

__device__ __forceinline__ ull fma2(ull a, ull b, ull c){
    ull d;
    asm("fma.rn.f32x2 %0, %1, %2, %3;" : "=l"(d) : "l"(a), "l"(b), "l"(c));
    return d;
}
__device__ __forceinline__ float2 upk(ull v){
    float2 f; asm("mov.b64 {%0,%1}, %2;" : "=f"(f.x), "=f"(f.y) : "l"(v)); return f;
}

// ---------------- scratch ----------------
__device__ __align__(16) float  d_pt[B_*N_*C1];
__device__ __align__(16) float4 d_xyz4[B_*N_];
__device__              int     d_knn[B_*S_*K_];
__device__ __align__(16) float  d_buf0[(size_t)B_*S_*K_*C1];   // [bs][k][co]
__device__ __align__(16) float  d_buf1[(size_t)B_*S_*K_*C2];   // [bs][k][co]
__device__              float   d_maxb[B_*S_*C3];
__device__              float   d_minb[B_*S_*C3];
__device__              float   d_ps0[4096*C1], d_pq0[4096*C1];
__device__              float   d_ps1[4096*C2], d_pq1[4096*C2];
__device__              float   d_ps2[8192*C3], d_pq2[8192*C3];
__device__              float   d_mean0[C1], d_istd0[C1];
__device__              float   d_mean1[C2], d_istd1[C2];
__device__              float   d_mean2[C3], d_istd2[C3];

// ---------------- transpose points ----------------
__global__ void k_tr(const float* __restrict__ pts){
    __shared__ float tile[32][33];
    int b = blockIdx.z, c0 = blockIdx.y*32, n0 = blockIdx.x*32;
    for (int j = threadIdx.y; j < 32; j += 8)
        tile[j][threadIdx.x] = pts[((size_t)(b*C1 + c0 + j))*N_ + n0 + threadIdx.x];
    __syncthreads();
    for (int j = threadIdx.y; j < 32; j += 8)
        d_pt[((size_t)(b*N_ + n0 + j))*C1 + c0 + threadIdx.x] = tile[threadIdx.x][j];
}

// ---------------- xyz4 + new_xyz ----------------
__global__ void k_xyz(const float* __restrict__ xyz, float* __restrict__ out){
    int i = blockIdx.x*blockDim.x + threadIdx.x;
    if (i >= B_*N_) return;
    int b = i / N_, n = i % N_;
    float x = xyz[(b*3+0)*N_+n], y = xyz[(b*3+1)*N_+n], z = xyz[(b*3+2)*N_+n];
    d_xyz4[i] = make_float4(x, y, z, fmaf(z,z, fmaf(y,y, x*x)));
    if (n < S_){
        out[(b*3+0)*S_+n] = x;
        out[(b*3+1)*S_+n] = y;
        out[(b*3+2)*S_+n] = z;
    }
}

// ---------------- KNN: warp per query; smem tiles; short-chain insertion ----------------
__global__ void __launch_bounds__(256) k_knn(){
    __shared__ float4 tile[512];
    int t = threadIdx.x;
    int lane = t & 31, w = t >> 5;
    int qg = blockIdx.x*8 + w;
    int b = qg >> 12;
    int s = qg & (S_ - 1);
    const float4* base = &d_xyz4[b*N_];
    float4 c4 = base[s];
    float cx = c4.x, cy = c4.y, cz = c4.z, cs = c4.w;

    float bd = FINF;
    int   bi = 0;
    float cm = FINF;

    for (int j0 = 0; j0 < N_; j0 += 512){
        tile[t]       = base[j0 + t];
        tile[t + 256] = base[j0 + t + 256];
        __syncthreads();
        for (int c = 0; c < 16; c++){
            float4 p = tile[c*32 + lane];
            float d = (cs + p.w) - 2.0f*fmaf(cz,p.z, fmaf(cy,p.y, cx*p.x));
            unsigned m = __ballot_sync(FULLM, d < cm);
            if (m){
                do {
                    int src = __ffs(m) - 1; m &= m - 1;
                    float cd = __shfl_sync(FULLM, d, src);
                    int   cn = j0 + c*32 + src;
                    float pk_ = __shfl_up_sync(FULLM, bd, 1);
                    int   pi_ = __shfl_up_sync(FULLM, bi, 1);
                    if (lane == 0) pk_ = -FINF;
                    if (bd > cd){
                        bool f = (pk_ <= cd);
                        bd = f ? cd : pk_;
                        bi = f ? cn : pi_;
                    }
                } while (m);
                cm = __shfl_sync(FULLM, bd, 31);
            }
        }
        __syncthreads();
    }
    d_knn[qg*K_ + lane] = bi;
}

// ============ layer0: gather + GEMM, ci-paired f32x2, [k][ci] layout ============
// 2 points/block, 2 warps/point (each warp: 32 k x 32 co), tile 8co x 4k / thread
__global__ void __launch_bounds__(128, 4) k_g0(const float* __restrict__ W0g){
    extern __shared__ float dyn[];
    float* sx = dyn;            // 2 pts * 32 k * 68
    float* sw = dyn + 2*32*68;  // 64 co * 68
    __shared__ float ssum[C1], ssq[C1];
    int t = threadIdx.x;
    int bs0 = blockIdx.x*2;

    { // weights: ci' 0..63 = points(ref 3..66), 64..66 = dir(ref 0..2), 67 = 0
        int co = t >> 1, h = t & 1;
        float* r = sw + co*68;
        for (int ci = h*34; ci < h*34 + 34; ci++){
            float v;
            if (ci < 64)      v = W0g[co*C0 + 3 + ci];
            else if (ci < 67) v = W0g[co*C0 + (ci - 64)];
            else              v = 0.f;
            r[ci] = v;
        }
    }
    if (t < C1){ ssum[t] = 0.f; ssq[t] = 0.f; }

    { // gather: 2 threads per (pt,k)
        int pt = t >> 6, r6 = t & 63, k = r6 >> 1, h = r6 & 1;
        int bs = bs0 + pt;
        int b = bs >> 12, s = bs & (S_ - 1);
        int idx = d_knn[bs*K_ + k];
        float* xr = sx + pt*2176 + k*68;
        const float4* prow = (const float4*)&d_pt[((size_t)(b*N_ + idx))*C1];
        #pragma unroll
        for (int q = 0; q < 8; q++)
            *(float4*)(xr + (h*8 + q)*4) = prow[h*8 + q];
        if (h){
            float4 pc = d_xyz4[b*N_ + s], pn = d_xyz4[b*N_ + idx];
            *(float4*)(xr + 64) = make_float4(pn.x-pc.x, pn.y-pc.y, pn.z-pc.z, 0.f);
        }
    }
    __syncthreads();

    int lane = t & 31, wp = t >> 5;
    int pt = wp >> 1, wco = (wp & 1)*32;
    int kq = lane & 7, cog = lane >> 3;       // k = kq+8kk, co = wco+cog+4cc
    const float* xb = sx + pt*2176 + kq*68;
    const float* wb = sw + (wco + cog)*68;
    ull acc[8][4];
    #pragma unroll
    for (int cc = 0; cc < 8; cc++)
        #pragma unroll
        for (int kk = 0; kk < 4; kk++) acc[cc][kk] = 0ull;

    for (int ci0 = 0; ci0 < 68; ci0 += 4){
        ulonglong2 xv[4];
        #pragma unroll
        for (int kk = 0; kk < 4; kk++)
            xv[kk] = *(const ulonglong2*)(xb + kk*544 + ci0);
        #pragma unroll
        for (int cc = 0; cc < 8; cc++){
            ulonglong2 wv = *(const ulonglong2*)(wb + cc*272 + ci0);
            #pragma unroll
            for (int kk = 0; kk < 4; kk++){
                acc[cc][kk] = fma2(xv[kk].x, wv.x, acc[cc][kk]);
                acc[cc][kk] = fma2(xv[kk].y, wv.y, acc[cc][kk]);
            }
        }
    }

    int bs = bs0 + pt;
    float* ob = d_buf0 + (size_t)bs*(K_*C1);
    float ls[8], lq[8];
    #pragma unroll
    for (int cc = 0; cc < 8; cc++){
        int co = wco + cog + 4*cc;
        float s_ = 0.f, q_ = 0.f;
        #pragma unroll
        for (int kk = 0; kk < 4; kk++){
            float2 h2 = upk(acc[cc][kk]);
            float y = h2.x + h2.y;
            ob[(kq + 8*kk)*C1 + co] = y;
            s_ += y; q_ = fmaf(y, y, q_);
        }
        ls[cc] = s_; lq[cc] = q_;
    }
    #pragma unroll
    for (int cc = 0; cc < 8; cc++){
        ls[cc] += __shfl_xor_sync(FULLM, ls[cc], 1);
        ls[cc] += __shfl_xor_sync(FULLM, ls[cc], 2);
        ls[cc] += __shfl_xor_sync(FULLM, ls[cc], 4);
        lq[cc] += __shfl_xor_sync(FULLM, lq[cc], 1);
        lq[cc] += __shfl_xor_sync(FULLM, lq[cc], 2);
        lq[cc] += __shfl_xor_sync(FULLM, lq[cc], 4);
    }
    if (kq == 0){
        #pragma unroll
        for (int cc = 0; cc < 8; cc++){
            int co = wco + cog + 4*cc;
            atomicAdd(&ssum[co], ls[cc]);
            atomicAdd(&ssq [co], lq[cc]);
        }
    }
    __syncthreads();
    if (t < C1){
        d_ps0[blockIdx.x*C1 + t] = ssum[t];
        d_pq0[blockIdx.x*C1 + t] = ssq[t];
    }
}

// ---------------- stats finalize ----------------
__global__ void k_stats(int which){
    const float *ps, *pq; float *mean, *istd; int nblk, C;
    if (which == 0){ ps = d_ps0; pq = d_pq0; mean = d_mean0; istd = d_istd0; nblk = 4096; C = 64; }
    else if (which == 1){ ps = d_ps1; pq = d_pq1; mean = d_mean1; istd = d_istd1; nblk = 4096; C = 64; }
    else { ps = d_ps2; pq = d_pq2; mean = d_mean2; istd = d_istd2; nblk = 8192; C = 128; }
    int c = blockIdx.x;
    __shared__ float rs[256], rq[256];
    float s = 0.f, q = 0.f;
    for (int i = threadIdx.x; i < nblk; i += 256){ s += ps[i*C + c]; q += pq[i*C + c]; }
    rs[threadIdx.x] = s; rq[threadIdx.x] = q;
    __syncthreads();
    for (int o = 128; o; o >>= 1){
        if (threadIdx.x < o){ rs[threadIdx.x] += rs[threadIdx.x+o]; rq[threadIdx.x] += rq[threadIdx.x+o]; }
        __syncthreads();
    }
    if (threadIdx.x == 0){
        float cnt = (float)(B_*S_*K_);
        float m = rs[0] / cnt;
        float v = rq[0] / cnt - m*m;
        mean[c] = m;
        istd[c] = rsqrtf(v + 1e-5f);
    }
}

// ============ layer1: bn0+act load, GEMM 64x64 ============
__global__ void __launch_bounds__(128, 4) k_g1(const float* __restrict__ W1g,
                     const float* __restrict__ g0, const float* __restrict__ b0){
    extern __shared__ float dyn[];
    float* sx = dyn;            // 2*32*68
    float* sw = dyn + 2*32*68;  // 64*68
    __shared__ float ssum[C2], ssq[C2];
    __shared__ __align__(16) float sa[C1], sb[C1];
    int t = threadIdx.x;
    int bs0 = blockIdx.x*2;

    {
        int co = t >> 1, h = t & 1;
        const float* wr = W1g + co*C1;
        float* r = sw + co*68;
        #pragma unroll
        for (int ci = 0; ci < 32; ci++) r[h*32 + ci] = wr[h*32 + ci];
    }
    if (t < C1){
        float a = d_istd0[t]*g0[t];
        sa[t] = a;
        sb[t] = fmaf(-d_mean0[t], a, b0[t]);
        ssum[t] = 0.f; ssq[t] = 0.f;
    }
    __syncthreads();

    {
        const float4* src = (const float4*)(d_buf0 + (size_t)bs0*(K_*C1));
        for (int e = t; e < 1024; e += 128){
            float4 v = src[e];
            int pt_ = e >> 9, r9 = e & 511, k = r9 >> 4, q = r9 & 15;
            float4 a4 = *(const float4*)(sa + q*4);
            float4 b4 = *(const float4*)(sb + q*4);
            float r;
            r = fmaf(v.x,a4.x,b4.x); v.x = r >= 0.f ? r : 0.1f*r;
            r = fmaf(v.y,a4.y,b4.y); v.y = r >= 0.f ? r : 0.1f*r;
            r = fmaf(v.z,a4.z,b4.z); v.z = r >= 0.f ? r : 0.1f*r;
            r = fmaf(v.w,a4.w,b4.w); v.w = r >= 0.f ? r : 0.1f*r;
            *(float4*)(sx + pt_*2176 + k*68 + q*4) = v;
        }
    }
    __syncthreads();

    int lane = t & 31, wp = t >> 5;
    int pt = wp >> 1, wco = (wp & 1)*32;
    int kq = lane & 7, cog = lane >> 3;
    const float* xb = sx + pt*2176 + kq*68;
    const float* wb = sw + (wco + cog)*68;
    ull acc[8][4];
    #pragma unroll
    for (int cc = 0; cc < 8; cc++)
        #pragma unroll
        for (int kk = 0; kk < 4; kk++) acc[cc][kk] = 0ull;

    for (int ci0 = 0; ci0 < 64; ci0 += 4){
        ulonglong2 xv[4];
        #pragma unroll
        for (int kk = 0; kk < 4; kk++)
            xv[kk] = *(const ulonglong2*)(xb + kk*544 + ci0);
        #pragma unroll
        for (int cc = 0; cc < 8; cc++){
            ulonglong2 wv = *(const ulonglong2*)(wb + cc*272 + ci0);
            #pragma unroll
            for (int kk = 0; kk < 4; kk++){
                acc[cc][kk] = fma2(xv[kk].x, wv.x, acc[cc][kk]);
                acc[cc][kk] = fma2(xv[kk].y, wv.y, acc[cc][kk]);
            }
        }
    }

    int bs = bs0 + pt;
    float* ob = d_buf1 + (size_t)bs*(K_*C2);
    float ls[8], lq[8];
    #pragma unroll
    for (int cc = 0; cc < 8; cc++){
        int co = wco + cog + 4*cc;
        float s_ = 0.f, q_ = 0.f;
        #pragma unroll
        for (int kk = 0; kk < 4; kk++){
            float2 h2 = upk(acc[cc][kk]);
            float y = h2.x + h2.y;
            ob[(kq + 8*kk)*C2 + co] = y;
            s_ += y; q_ = fmaf(y, y, q_);
        }
        ls[cc] = s_; lq[cc] = q_;
    }
    #pragma unroll
    for (int cc = 0; cc < 8; cc++){
        ls[cc] += __shfl_xor_sync(FULLM, ls[cc], 1);
        ls[cc] += __shfl_xor_sync(FULLM, ls[cc], 2);
        ls[cc] += __shfl_xor_sync(FULLM, ls[cc], 4);
        lq[cc] += __shfl_xor_sync(FULLM, lq[cc], 1);
        lq[cc] += __shfl_xor_sync(FULLM, lq[cc], 2);
        lq[cc] += __shfl_xor_sync(FULLM, lq[cc], 4);
    }
    if (kq == 0){
        #pragma unroll
        for (int cc = 0; cc < 8; cc++){
            int co = wco + cog + 4*cc;
            atomicAdd(&ssum[co], ls[cc]);
            atomicAdd(&ssq [co], lq[cc]);
        }
    }
    __syncthreads();
    if (t < C2){
        d_ps1[blockIdx.x*C2 + t] = ssum[t];
        d_pq1[blockIdx.x*C2 + t] = ssq[t];
    }
}

// ============ layer2: bn1+act, GEMM 128x64, max/min over k ============
// 1 point/block, 4 warps cover co 0..127
__global__ void __launch_bounds__(128, 4) k_g2(const float* __restrict__ W2g,
                     const float* __restrict__ g1, const float* __restrict__ b1){
    extern __shared__ float dyn[];
    float* sx = dyn;          // 32*68
    float* sw = dyn + 32*68;  // 128*68
    __shared__ float ssum[C3], ssq[C3];
    __shared__ __align__(16) float sa[C2], sb[C2];
    int t = threadIdx.x;
    int bs = blockIdx.x;

    {
        int co = t;  // 128 rows
        const float4* wr = (const float4*)(W2g + co*C2);
        float* r = sw + co*68;
        #pragma unroll
        for (int q = 0; q < 16; q++)
            *(float4*)(r + q*4) = wr[q];
    }
    if (t < C2){
        float a = d_istd1[t]*g1[t];
        sa[t] = a;
        sb[t] = fmaf(-d_mean1[t], a, b1[t]);
    }
    if (t < C3){ ssum[t] = 0.f; ssq[t] = 0.f; }
    __syncthreads();

    {
        const float4* src = (const float4*)(d_buf1 + (size_t)bs*(K_*C2));
        for (int e = t; e < 512; e += 128){
            float4 v = src[e];
            int k = e >> 4, q = e & 15;
            float4 a4 = *(const float4*)(sa + q*4);
            float4 b4 = *(const float4*)(sb + q*4);
            float r;
            r = fmaf(v.x,a4.x,b4.x); v.x = r >= 0.f ? r : 0.1f*r;
            r = fmaf(v.y,a4.y,b4.y); v.y = r >= 0.f ? r : 0.1f*r;
            r = fmaf(v.z,a4.z,b4.z); v.z = r >= 0.f ? r : 0.1f*r;
            r = fmaf(v.w,a4.w,b4.w); v.w = r >= 0.f ? r : 0.1f*r;
            *(float4*)(sx + k*68 + q*4) = v;
        }
    }
    __syncthreads();

    int lane = t & 31, wp = t >> 5;
    int wco = wp*32;
    int kq = lane & 7, cog = lane >> 3;
    const float* xb = sx + kq*68;
    const float* wb = sw + (wco + cog)*68;
    ull acc[8][4];
    #pragma unroll
    for (int cc = 0; cc < 8; cc++)
        #pragma unroll
        for (int kk = 0; kk < 4; kk++) acc[cc][kk] = 0ull;

    for (int ci0 = 0; ci0 < 64; ci0 += 4){
        ulonglong2 xv[4];
        #pragma unroll
        for (int kk = 0; kk < 4; kk++)
            xv[kk] = *(const ulonglong2*)(xb + kk*544 + ci0);
        #pragma unroll
        for (int cc = 0; cc < 8; cc++){
            ulonglong2 wv = *(const ulonglong2*)(wb + cc*272 + ci0);
            #pragma unroll
            for (int kk = 0; kk < 4; kk++){
                acc[cc][kk] = fma2(xv[kk].x, wv.x, acc[cc][kk]);
                acc[cc][kk] = fma2(xv[kk].y, wv.y, acc[cc][kk]);
            }
        }
    }

    #pragma unroll
    for (int cc = 0; cc < 8; cc++){
        int co = wco + cog + 4*cc;
        float mx = -FINF, mn = FINF, s_ = 0.f, q_ = 0.f;
        #pragma unroll
        for (int kk = 0; kk < 4; kk++){
            float2 h2 = upk(acc[cc][kk]);
            float y = h2.x + h2.y;
            mx = fmaxf(mx, y); mn = fminf(mn, y);
            s_ += y; q_ = fmaf(y, y, q_);
        }
        #pragma unroll
        for (int o = 1; o <= 4; o <<= 1){
            mx = fmaxf(mx, __shfl_xor_sync(FULLM, mx, o));
            mn = fminf(mn, __shfl_xor_sync(FULLM, mn, o));
            s_ += __shfl_xor_sync(FULLM, s_, o);
            q_ += __shfl_xor_sync(FULLM, q_, o);
        }
        if (kq == 0){
            d_maxb[bs*C3 + co] = mx;
            d_minb[bs*C3 + co] = mn;
            atomicAdd(&ssum[co], s_);
            atomicAdd(&ssq [co], q_);
        }
    }
    __syncthreads();
    if (t < C3){
        d_ps2[blockIdx.x*C3 + t] = ssum[t];
        d_pq2[blockIdx.x*C3 + t] = ssq[t];
    }
}

// ---------------- final ----------------
__global__ void k_final(const float* __restrict__ g2, const float* __restrict__ b2,
                        float* __restrict__ out){
    int o = blockIdx.x*blockDim.x + threadIdx.x;
    if (o >= B_*C3*S_) return;
    int s  = o & (S_ - 1);
    int co = (o >> 12) & 127;
    int b  = o >> 19;
    float a = d_istd2[co]*g2[co];
    float base = fmaf(-d_mean2[co], a, b2[co]);
    int bs = b*S_ + s;
    float yv = (a > 0.f) ? d_maxb[bs*C3 + co] : ((a < 0.f) ? d_minb[bs*C3 + co] : 0.f);
    float r = fmaf(yv, a, base);
    out[B_*3*S_ + o] = r >= 0.f ? r : 0.1f*r;
}

extern "C" void kernel_launch(void* const* d_in, const int* in_sizes, int n_in,
                              void* d_out, int out_size){
    const float* xyz    = (const float*)d_in[0];
    const float* points = (const float*)d_in[1];
    const float* W0     = (const float*)d_in[2];
    const float* W1     = (const float*)d_in[3];
    const float* W2     = (const float*)d_in[4];
    const float* g0     = (const float*)d_in[5];
    const float* b0     = (const float*)d_in[6];
    const float* g1     = (const float*)d_in[7];
    const float* b1     = (const float*)d_in[8];
    const float* g2     = (const float*)d_in[9];
    const float* b2     = (const float*)d_in[10];
    float* out = (float*)d_out;

    const int smem0 = (2*32*68 + 64*68) * 4;    // 34,816
    const int smem1 = (2*32*68 + 64*68) * 4;    // 34,816
    const int smem2 = (32*68 + 128*68) * 4;     // 43,520
    cudaFuncSetAttribute(k_g0, cudaFuncAttributeMaxDynamicSharedMemorySize, smem0);
    cudaFuncSetAttribute(k_g1, cudaFuncAttributeMaxDynamicSharedMemorySize, smem1);
    cudaFuncSetAttribute(k_g2, cudaFuncAttributeMaxDynamicSharedMemorySize, smem2);

    k_tr  <<<dim3(N_/32, C1/32, B_), dim3(32,8)>>>(points);
    k_xyz <<<(B_*N_ + 255)/256, 256>>>(xyz, out);
    k_knn <<<B_*S_/8, 256>>>();
    k_g0  <<<B_*S_/2, 128, smem0>>>(W0);
    k_stats<<<64, 256>>>(0);
    k_g1  <<<B_*S_/2, 128, smem1>>>(W1, g0, b0);
    k_stats<<<64, 256>>>(1);
    k_g2  <<<B_*S_, 128, smem2>>>(W2, g1, b1);
    k_stats<<<128, 256>>>(2);
    k_final<<<(B_*C3*S_ + 255)/256, 256>>>(g2, b2, out);
}

// round 7
// speedup vs baseline: 1.0892x; 1.0892x over previous
#include <cuda_runtime.h>

#define B_ 2
#define N_ 16384
#define S_ 4096
#define K_ 32
#define C0 67
#define C1 64
#define C2 64
#define C3 128
#define ST 36
#define FULLM 0xffffffffu
#define FINF 3.402823466e38f

typedef unsigned long long ull;

__device__ __forceinline__ ull fma2(ull a, ull b, ull c){
    ull d;
    asm("fma.rn.f32x2 %0, %1, %2, %3;" : "=l"(d) : "l"(a), "l"(b), "l"(c));
    return d;
}
__device__ __forceinline__ ull pk(float lo, float hi){
    ull r; asm("mov.b64 %0, {%1,%2};" : "=l"(r) : "f"(lo), "f"(hi)); return r;
}
__device__ __forceinline__ float2 upk(ull v){
    float2 f; asm("mov.b64 {%0,%1}, %2;" : "=f"(f.x), "=f"(f.y) : "l"(v)); return f;
}

// ---------------- scratch ----------------
__device__ __align__(16) float  d_pt[B_*N_*C1];
__device__ __align__(16) float4 d_xyz4[B_*N_];
__device__              int     d_knn[B_*S_*K_];
__device__ __align__(16) float  d_buf0[(size_t)B_*S_*C1*K_];   // [bs][co][k]
__device__ __align__(16) float  d_buf1[(size_t)B_*S_*C2*K_];   // [bs][co][k]
__device__              float   d_maxb[B_*S_*C3];
__device__              float   d_minb[B_*S_*C3];
__device__              float   d_ps0[4096*C1], d_pq0[4096*C1];
__device__              float   d_ps1[4096*C2], d_pq1[4096*C2];
__device__              float   d_ps2[8192*C3], d_pq2[8192*C3];
__device__              float   d_mean0[C1], d_istd0[C1];
__device__              float   d_mean1[C2], d_istd1[C2];
__device__              float   d_mean2[C3], d_istd2[C3];

// ---------------- transpose points ----------------
__global__ void k_tr(const float* __restrict__ pts){
    __shared__ float tile[32][33];
    int b = blockIdx.z, c0 = blockIdx.y*32, n0 = blockIdx.x*32;
    for (int j = threadIdx.y; j < 32; j += 8)
        tile[j][threadIdx.x] = pts[((size_t)(b*C1 + c0 + j))*N_ + n0 + threadIdx.x];
    __syncthreads();
    for (int j = threadIdx.y; j < 32; j += 8)
        d_pt[((size_t)(b*N_ + n0 + j))*C1 + c0 + threadIdx.x] = tile[threadIdx.x][j];
}

// ---------------- xyz4 + new_xyz ----------------
__global__ void k_xyz(const float* __restrict__ xyz, float* __restrict__ out){
    int i = blockIdx.x*blockDim.x + threadIdx.x;
    if (i >= B_*N_) return;
    int b = i / N_, n = i % N_;
    float x = xyz[(b*3+0)*N_+n], y = xyz[(b*3+1)*N_+n], z = xyz[(b*3+2)*N_+n];
    d_xyz4[i] = make_float4(x, y, z, fmaf(z,z, fmaf(y,y, x*x)));
    if (n < S_){
        out[(b*3+0)*S_+n] = x;
        out[(b*3+1)*S_+n] = y;
        out[(b*3+2)*S_+n] = z;
    }
}

// ---------------- KNN (proven R5 version) ----------------
__global__ void __launch_bounds__(256) k_knn(){
    __shared__ float4 tile[512];
    int t = threadIdx.x;
    int lane = t & 31, w = t >> 5;
    int qg = blockIdx.x*8 + w;
    int b = qg >> 12;
    int s = qg & (S_ - 1);
    const float4* base = &d_xyz4[b*N_];
    float4 c4 = base[s];
    float cx = c4.x, cy = c4.y, cz = c4.z, cs = c4.w;

    float bd = FINF;
    int   bi = 0;
    float cm = FINF;

    for (int j0 = 0; j0 < N_; j0 += 512){
        tile[t]       = base[j0 + t];
        tile[t + 256] = base[j0 + t + 256];
        __syncthreads();
        for (int c = 0; c < 16; c++){
            float4 p = tile[c*32 + lane];
            float d = (cs + p.w) - 2.0f*fmaf(cz,p.z, fmaf(cy,p.y, cx*p.x));
            unsigned m = __ballot_sync(FULLM, d < cm);
            if (m){
                do {
                    int src = __ffs(m) - 1; m &= m - 1;
                    float cd = __shfl_sync(FULLM, d, src);
                    int   cn = j0 + c*32 + src;
                    float pk_ = __shfl_up_sync(FULLM, bd, 1);
                    int   pi_ = __shfl_up_sync(FULLM, bi, 1);
                    if (lane == 0) pk_ = -FINF;
                    if (bd > cd){
                        bool f = (pk_ <= cd);
                        bd = f ? cd : pk_;
                        bi = f ? cn : pi_;
                    }
                } while (m);
                cm = __shfl_sync(FULLM, bd, 31);
            }
        }
        __syncthreads();
    }
    d_knn[qg*K_ + lane] = bi;
}

// ============ layer0: 256 thr, 4 pts, 8 warps = 4pt x 2co-half ============
// warp: 32co x 32k; thread: 4co x 8k; acc[4][4] (f32x2 over k)
__global__ void __launch_bounds__(256, 4) k_g0(const float* __restrict__ W0g){
    extern __shared__ float dyn[];
    float* sx = dyn;                 // 4 * C0 * ST
    float* sw = dyn + 4*C0*ST;       // C0 * 64  [ci][co]
    __shared__ float ssum[C1], ssq[C1];
    int t = threadIdx.x;
    int bs0 = blockIdx.x*4;

    for (int e = t; e < C0*64; e += 256){
        int ci = e >> 6, co = e & 63;
        sw[e] = W0g[co*C0 + ci];
    }
    if (t < C1){ ssum[t] = 0.f; ssq[t] = 0.f; }

    { // gather: 2 threads per (pt,k); half h writes channels 8q+4h..+3
        int pair = t >> 1, half = t & 1;
        int pt = pair >> 5, k = pair & 31;
        int bs = bs0 + pt;
        int b = bs >> 12, s = bs & (S_ - 1);
        int idx = d_knn[bs*K_ + k];
        float* xr = &sx[pt*C0*ST];
        if (half){
            float4 pc = d_xyz4[b*N_ + s];
            float4 pn = d_xyz4[b*N_ + idx];
            xr[0*ST + k] = pn.x - pc.x;
            xr[1*ST + k] = pn.y - pc.y;
            xr[2*ST + k] = pn.z - pc.z;
        }
        const float4* prow = (const float4*)&d_pt[((size_t)(b*N_ + idx))*C1];
        #pragma unroll
        for (int q = 0; q < 8; q++){
            float4 v = prow[q*2 + half];
            int c = 3 + q*8 + half*4;
            xr[(c+0)*ST + k] = v.x;
            xr[(c+1)*ST + k] = v.y;
            xr[(c+2)*ST + k] = v.z;
            xr[(c+3)*ST + k] = v.w;
        }
    }
    __syncthreads();

    int lane = t & 31, wp = t >> 5;
    int pt = wp >> 1, coh = (wp & 1)*32;
    int kq = lane & 3, cog = lane >> 2;
    const float* xb = &sx[pt*C0*ST + kq*8];
    const float* wb = sw + coh + cog*4;
    ull acc[4][4];
    #pragma unroll
    for (int j = 0; j < 4; j++){ acc[j][0]=0; acc[j][1]=0; acc[j][2]=0; acc[j][3]=0; }

    for (int ci = 0; ci < C0; ci++){
        float4 xa = *(const float4*)(xb + ci*ST);
        float4 xc = *(const float4*)(xb + ci*ST + 4);
        ull x0 = pk(xa.x,xa.y), x1 = pk(xa.z,xa.w);
        ull x2 = pk(xc.x,xc.y), x3 = pk(xc.z,xc.w);
        float4 wv = *(const float4*)(wb + ci*64);
        float wj[4] = {wv.x, wv.y, wv.z, wv.w};
        #pragma unroll
        for (int j = 0; j < 4; j++){
            ull w2 = pk(wj[j], wj[j]);
            acc[j][0] = fma2(w2, x0, acc[j][0]);
            acc[j][1] = fma2(w2, x1, acc[j][1]);
            acc[j][2] = fma2(w2, x2, acc[j][2]);
            acc[j][3] = fma2(w2, x3, acc[j][3]);
        }
    }

    int bs = bs0 + pt;
    float* orow = &d_buf0[(size_t)bs*C1*K_];
    float ls[4], lq[4];
    #pragma unroll
    for (int j = 0; j < 4; j++){
        int co = coh + cog*4 + j;
        float2 a0 = upk(acc[j][0]), a1 = upk(acc[j][1]);
        float2 a2 = upk(acc[j][2]), a3 = upk(acc[j][3]);
        *(float4*)&orow[co*K_ + kq*8]     = make_float4(a0.x,a0.y,a1.x,a1.y);
        *(float4*)&orow[co*K_ + kq*8 + 4] = make_float4(a2.x,a2.y,a3.x,a3.y);
        ls[j] = ((a0.x+a0.y)+(a1.x+a1.y)) + ((a2.x+a2.y)+(a3.x+a3.y));
        float q0 = fmaf(a0.x,a0.x, fmaf(a0.y,a0.y, fmaf(a1.x,a1.x, a1.y*a1.y)));
        lq[j] = fmaf(a2.x,a2.x, fmaf(a2.y,a2.y, fmaf(a3.x,a3.x, fmaf(a3.y,a3.y, q0))));
    }
    #pragma unroll
    for (int j = 0; j < 4; j++){
        ls[j] += __shfl_xor_sync(FULLM, ls[j], 1);
        ls[j] += __shfl_xor_sync(FULLM, ls[j], 2);
        lq[j] += __shfl_xor_sync(FULLM, lq[j], 1);
        lq[j] += __shfl_xor_sync(FULLM, lq[j], 2);
    }
    if (kq == 0){
        #pragma unroll
        for (int j = 0; j < 4; j++){
            atomicAdd(&ssum[coh + cog*4 + j], ls[j]);
            atomicAdd(&ssq [coh + cog*4 + j], lq[j]);
        }
    }
    __syncthreads();
    if (t < C1){
        d_ps0[blockIdx.x*C1 + t] = ssum[t];
        d_pq0[blockIdx.x*C1 + t] = ssq[t];
    }
}

// ---------------- stats finalize ----------------
__global__ void k_stats(int which){
    const float *ps, *pq; float *mean, *istd; int nblk, C;
    if (which == 0){ ps = d_ps0; pq = d_pq0; mean = d_mean0; istd = d_istd0; nblk = 2048; C = 64; }
    else if (which == 1){ ps = d_ps1; pq = d_pq1; mean = d_mean1; istd = d_istd1; nblk = 2048; C = 64; }
    else { ps = d_ps2; pq = d_pq2; mean = d_mean2; istd = d_istd2; nblk = 4096; C = 128; }
    int c = blockIdx.x;
    __shared__ float rs[256], rq[256];
    float s = 0.f, q = 0.f;
    for (int i = threadIdx.x; i < nblk; i += 256){ s += ps[i*C + c]; q += pq[i*C + c]; }
    rs[threadIdx.x] = s; rq[threadIdx.x] = q;
    __syncthreads();
    for (int o = 128; o; o >>= 1){
        if (threadIdx.x < o){ rs[threadIdx.x] += rs[threadIdx.x+o]; rq[threadIdx.x] += rq[threadIdx.x+o]; }
        __syncthreads();
    }
    if (threadIdx.x == 0){
        float cnt = (float)(B_*S_*K_);
        float m = rs[0] / cnt;
        float v = rq[0] / cnt - m*m;
        mean[c] = m;
        istd[c] = rsqrtf(v + 1e-5f);
    }
}

// ============ layer1: 256 thr, 4 pts ============
__global__ void __launch_bounds__(256, 4) k_g1(const float* __restrict__ W1g,
                     const float* __restrict__ g0, const float* __restrict__ b0){
    extern __shared__ float dyn[];
    float* sx = dyn;                 // 4 * C1 * ST
    float* sw = dyn + 4*C1*ST;       // C1 * 64
    __shared__ float ssum[C2], ssq[C2], sa[C1], sb[C1];
    int t = threadIdx.x;
    int bs0 = blockIdx.x*4;

    for (int e = t; e < C1*64; e += 256){
        int ci = e >> 6, co = e & 63;
        sw[e] = W1g[co*C1 + ci];
    }
    if (t < C1){
        float a = d_istd0[t]*g0[t];
        sa[t] = a;
        sb[t] = fmaf(-d_mean0[t], a, b0[t]);
        ssum[t] = 0.f; ssq[t] = 0.f;
    }
    __syncthreads();

    {
        const float4* src = (const float4*)&d_buf0[(size_t)bs0*C1*K_];
        for (int e = t; e < 2048; e += 256){
            float4 v = src[e];
            int p = e >> 9, r2 = e & 511;
            int ci = r2 >> 3, k4 = (r2 & 7)*4;
            float a = sa[ci], bb = sb[ci], r;
            r = fmaf(v.x,a,bb); v.x = r >= 0.f ? r : 0.1f*r;
            r = fmaf(v.y,a,bb); v.y = r >= 0.f ? r : 0.1f*r;
            r = fmaf(v.z,a,bb); v.z = r >= 0.f ? r : 0.1f*r;
            r = fmaf(v.w,a,bb); v.w = r >= 0.f ? r : 0.1f*r;
            *(float4*)&sx[p*C1*ST + ci*ST + k4] = v;
        }
    }
    __syncthreads();

    int lane = t & 31, wp = t >> 5;
    int pt = wp >> 1, coh = (wp & 1)*32;
    int kq = lane & 3, cog = lane >> 2;
    const float* xb = &sx[pt*C1*ST + kq*8];
    const float* wb = sw + coh + cog*4;
    ull acc[4][4];
    #pragma unroll
    for (int j = 0; j < 4; j++){ acc[j][0]=0; acc[j][1]=0; acc[j][2]=0; acc[j][3]=0; }

    for (int ci = 0; ci < C1; ci++){
        float4 xa = *(const float4*)(xb + ci*ST);
        float4 xc = *(const float4*)(xb + ci*ST + 4);
        ull x0 = pk(xa.x,xa.y), x1 = pk(xa.z,xa.w);
        ull x2 = pk(xc.x,xc.y), x3 = pk(xc.z,xc.w);
        float4 wv = *(const float4*)(wb + ci*64);
        float wj[4] = {wv.x, wv.y, wv.z, wv.w};
        #pragma unroll
        for (int j = 0; j < 4; j++){
            ull w2 = pk(wj[j], wj[j]);
            acc[j][0] = fma2(w2, x0, acc[j][0]);
            acc[j][1] = fma2(w2, x1, acc[j][1]);
            acc[j][2] = fma2(w2, x2, acc[j][2]);
            acc[j][3] = fma2(w2, x3, acc[j][3]);
        }
    }

    int bs = bs0 + pt;
    float* orow = &d_buf1[(size_t)bs*C2*K_];
    float ls[4], lq[4];
    #pragma unroll
    for (int j = 0; j < 4; j++){
        int co = coh + cog*4 + j;
        float2 a0 = upk(acc[j][0]), a1 = upk(acc[j][1]);
        float2 a2 = upk(acc[j][2]), a3 = upk(acc[j][3]);
        *(float4*)&orow[co*K_ + kq*8]     = make_float4(a0.x,a0.y,a1.x,a1.y);
        *(float4*)&orow[co*K_ + kq*8 + 4] = make_float4(a2.x,a2.y,a3.x,a3.y);
        ls[j] = ((a0.x+a0.y)+(a1.x+a1.y)) + ((a2.x+a2.y)+(a3.x+a3.y));
        float q0 = fmaf(a0.x,a0.x, fmaf(a0.y,a0.y, fmaf(a1.x,a1.x, a1.y*a1.y)));
        lq[j] = fmaf(a2.x,a2.x, fmaf(a2.y,a2.y, fmaf(a3.x,a3.x, fmaf(a3.y,a3.y, q0))));
    }
    #pragma unroll
    for (int j = 0; j < 4; j++){
        ls[j] += __shfl_xor_sync(FULLM, ls[j], 1);
        ls[j] += __shfl_xor_sync(FULLM, ls[j], 2);
        lq[j] += __shfl_xor_sync(FULLM, lq[j], 1);
        lq[j] += __shfl_xor_sync(FULLM, lq[j], 2);
    }
    if (kq == 0){
        #pragma unroll
        for (int j = 0; j < 4; j++){
            atomicAdd(&ssum[coh + cog*4 + j], ls[j]);
            atomicAdd(&ssq [coh + cog*4 + j], lq[j]);
        }
    }
    __syncthreads();
    if (t < C2){
        d_ps1[blockIdx.x*C2 + t] = ssum[t];
        d_pq1[blockIdx.x*C2 + t] = ssq[t];
    }
}

// ============ layer2: 256 thr, 2 pts, 8 warps = 2pt x 4co-group ============
__global__ void __launch_bounds__(256, 4) k_g2(const float* __restrict__ W2g,
                     const float* __restrict__ g1, const float* __restrict__ b1){
    extern __shared__ float dyn[];
    float* sx = dyn;                 // 2 * C2 * ST
    float* sw = dyn + 2*C2*ST;       // C2 * 128  [ci][co]
    __shared__ float sa[C2], sb[C2], ssum[C3], ssq[C3];
    int t = threadIdx.x;
    int bs0 = blockIdx.x*2;

    for (int e = t; e < C2*C3; e += 256){
        int ci = e >> 7, co = e & 127;
        sw[e] = W2g[co*C2 + ci];
    }
    if (t < C2){
        float a = d_istd1[t]*g1[t];
        sa[t] = a;
        sb[t] = fmaf(-d_mean1[t], a, b1[t]);
    }
    if (t < C3){ ssum[t] = 0.f; ssq[t] = 0.f; }
    __syncthreads();

    {
        const float4* src = (const float4*)&d_buf1[(size_t)bs0*C2*K_];
        for (int e = t; e < 1024; e += 256){
            float4 v = src[e];
            int p = e >> 9, r2 = e & 511;
            int ci = r2 >> 3, k4 = (r2 & 7)*4;
            float a = sa[ci], bb = sb[ci], r;
            r = fmaf(v.x,a,bb); v.x = r >= 0.f ? r : 0.1f*r;
            r = fmaf(v.y,a,bb); v.y = r >= 0.f ? r : 0.1f*r;
            r = fmaf(v.z,a,bb); v.z = r >= 0.f ? r : 0.1f*r;
            r = fmaf(v.w,a,bb); v.w = r >= 0.f ? r : 0.1f*r;
            *(float4*)&sx[p*C2*ST + ci*ST + k4] = v;
        }
    }
    __syncthreads();

    int lane = t & 31, wp = t >> 5;
    int pt = wp >> 2, coh = (wp & 3)*32;
    int kq = lane & 3, cog = lane >> 2;
    const float* xb = &sx[pt*C2*ST + kq*8];
    const float* wb = sw + coh + cog*4;
    ull acc[4][4];
    #pragma unroll
    for (int j = 0; j < 4; j++){ acc[j][0]=0; acc[j][1]=0; acc[j][2]=0; acc[j][3]=0; }

    for (int ci = 0; ci < C2; ci++){
        float4 xa = *(const float4*)(xb + ci*ST);
        float4 xc = *(const float4*)(xb + ci*ST + 4);
        ull x0 = pk(xa.x,xa.y), x1 = pk(xa.z,xa.w);
        ull x2 = pk(xc.x,xc.y), x3 = pk(xc.z,xc.w);
        float4 wv = *(const float4*)(wb + ci*128);
        float wj[4] = {wv.x, wv.y, wv.z, wv.w};
        #pragma unroll
        for (int j = 0; j < 4; j++){
            ull w2 = pk(wj[j], wj[j]);
            acc[j][0] = fma2(w2, x0, acc[j][0]);
            acc[j][1] = fma2(w2, x1, acc[j][1]);
            acc[j][2] = fma2(w2, x2, acc[j][2]);
            acc[j][3] = fma2(w2, x3, acc[j][3]);
        }
    }

    int bs = bs0 + pt;
    #pragma unroll
    for (int j = 0; j < 4; j++){
        int co = coh + cog*4 + j;
        float2 a0 = upk(acc[j][0]), a1 = upk(acc[j][1]);
        float2 a2 = upk(acc[j][2]), a3 = upk(acc[j][3]);
        float mx = fmaxf(fmaxf(fmaxf(a0.x,a0.y),fmaxf(a1.x,a1.y)),
                         fmaxf(fmaxf(a2.x,a2.y),fmaxf(a3.x,a3.y)));
        float mn = fminf(fminf(fminf(a0.x,a0.y),fminf(a1.x,a1.y)),
                         fminf(fminf(a2.x,a2.y),fminf(a3.x,a3.y)));
        float s_ = ((a0.x+a0.y)+(a1.x+a1.y)) + ((a2.x+a2.y)+(a3.x+a3.y));
        float q0 = fmaf(a0.x,a0.x, fmaf(a0.y,a0.y, fmaf(a1.x,a1.x, a1.y*a1.y)));
        float q_ = fmaf(a2.x,a2.x, fmaf(a2.y,a2.y, fmaf(a3.x,a3.x, fmaf(a3.y,a3.y, q0))));
        mx = fmaxf(mx, __shfl_xor_sync(FULLM, mx, 1));
        mx = fmaxf(mx, __shfl_xor_sync(FULLM, mx, 2));
        mn = fminf(mn, __shfl_xor_sync(FULLM, mn, 1));
        mn = fminf(mn, __shfl_xor_sync(FULLM, mn, 2));
        s_ += __shfl_xor_sync(FULLM, s_, 1);
        s_ += __shfl_xor_sync(FULLM, s_, 2);
        q_ += __shfl_xor_sync(FULLM, q_, 1);
        q_ += __shfl_xor_sync(FULLM, q_, 2);
        if (kq == 0){
            d_maxb[bs*C3 + co] = mx;
            d_minb[bs*C3 + co] = mn;
            atomicAdd(&ssum[co], s_);
            atomicAdd(&ssq [co], q_);
        }
    }
    __syncthreads();
    if (t < C3){
        d_ps2[blockIdx.x*C3 + t] = ssum[t];
        d_pq2[blockIdx.x*C3 + t] = ssq[t];
    }
}

// ---------------- final ----------------
__global__ void k_final(const float* __restrict__ g2, const float* __restrict__ b2,
                        float* __restrict__ out){
    int o = blockIdx.x*blockDim.x + threadIdx.x;
    if (o >= B_*C3*S_) return;
    int s  = o & (S_ - 1);
    int co = (o >> 12) & 127;
    int b  = o >> 19;
    float a = d_istd2[co]*g2[co];
    float base = fmaf(-d_mean2[co], a, b2[co]);
    int bs = b*S_ + s;
    float yv = (a > 0.f) ? d_maxb[bs*C3 + co] : ((a < 0.f) ? d_minb[bs*C3 + co] : 0.f);
    float r = fmaf(yv, a, base);
    out[B_*3*S_ + o] = r >= 0.f ? r : 0.1f*r;
}

extern "C" void kernel_launch(void* const* d_in, const int* in_sizes, int n_in,
                              void* d_out, int out_size){
    const float* xyz    = (const float*)d_in[0];
    const float* points = (const float*)d_in[1];
    const float* W0     = (const float*)d_in[2];
    const float* W1     = (const float*)d_in[3];
    const float* W2     = (const float*)d_in[4];
    const float* g0     = (const float*)d_in[5];
    const float* b0     = (const float*)d_in[6];
    const float* g1     = (const float*)d_in[7];
    const float* b1     = (const float*)d_in[8];
    const float* g2     = (const float*)d_in[9];
    const float* b2     = (const float*)d_in[10];
    float* out = (float*)d_out;

    const int smem0 = (4*C0*ST + C0*64) * 4;   // 55,744
    const int smem1 = (4*C1*ST + C1*64) * 4;   // 53,248
    const int smem2 = (2*C2*ST + C2*C3) * 4;   // 51,200
    cudaFuncSetAttribute(k_g0, cudaFuncAttributeMaxDynamicSharedMemorySize, smem0);
    cudaFuncSetAttribute(k_g1, cudaFuncAttributeMaxDynamicSharedMemorySize, smem1);
    cudaFuncSetAttribute(k_g2, cudaFuncAttributeMaxDynamicSharedMemorySize, smem2);

    k_tr  <<<dim3(N_/32, C1/32, B_), dim3(32,8)>>>(points);
    k_xyz <<<(B_*N_ + 255)/256, 256>>>(xyz, out);
    k_knn <<<B_*S_/8, 256>>>();
    k_g0  <<<B_*S_/4, 256, smem0>>>(W0);
    k_stats<<<64, 256>>>(0);
    k_g1  <<<B_*S_/4, 256, smem1>>>(W1, g0, b0);
    k_stats<<<64, 256>>>(1);
    k_g2  <<<B_*S_/2, 256, smem2>>>(W2, g1, b1);
    k_stats<<<128, 256>>>(2);
    k_final<<<(B_*C3*S_ + 255)/256, 256>>>(g2, b2, out);
}

// round 8
// speedup vs baseline: 1.1167x; 1.0252x over previous
#include <cuda_runtime.h>

#define B_ 2
#define N_ 16384
#define S_ 4096
#define K_ 32
#define C0 67
#define C1 64
#define C2 64
#define C3 128
#define ST 36
#define FULLM 0xffffffffu
#define FINF 3.402823466e38f

typedef unsigned long long ull;

__device__ __forceinline__ ull fma2(ull a, ull b, ull c){
    ull d;
    asm("fma.rn.f32x2 %0, %1, %2, %3;" : "=l"(d) : "l"(a), "l"(b), "l"(c));
    return d;
}
__device__ __forceinline__ ull pk(float lo, float hi){
    ull r; asm("mov.b64 %0, {%1,%2};" : "=l"(r) : "f"(lo), "f"(hi)); return r;
}
__device__ __forceinline__ float2 upk(ull v){
    float2 f; asm("mov.b64 {%0,%1}, %2;" : "=f"(f.x), "=f"(f.y) : "l"(v)); return f;
}

// ---------------- scratch ----------------
__device__ __align__(16) float  d_pt[B_*N_*C1];
__device__ __align__(16) float4 d_xyz4[B_*N_];
__device__              int     d_knn[B_*S_*K_];
__device__ __align__(16) float  d_buf0[(size_t)B_*S_*C1*K_];
__device__ __align__(16) float  d_buf1[(size_t)B_*S_*C2*K_];
__device__              float   d_maxb[B_*S_*C3];
__device__              float   d_minb[B_*S_*C3];
__device__              float   d_ps0[4096*C1], d_pq0[4096*C1];
__device__              float   d_ps1[4096*C2], d_pq1[4096*C2];
__device__              float   d_ps2[8192*C3], d_pq2[8192*C3];
__device__              float   d_mean0[C1], d_istd0[C1];
__device__              float   d_mean1[C2], d_istd1[C2];
__device__              float   d_mean2[C3], d_istd2[C3];

// ---------------- transpose points ----------------
__global__ void k_tr(const float* __restrict__ pts){
    __shared__ float tile[32][33];
    int b = blockIdx.z, c0 = blockIdx.y*32, n0 = blockIdx.x*32;
    for (int j = threadIdx.y; j < 32; j += 8)
        tile[j][threadIdx.x] = pts[((size_t)(b*C1 + c0 + j))*N_ + n0 + threadIdx.x];
    __syncthreads();
    for (int j = threadIdx.y; j < 32; j += 8)
        d_pt[((size_t)(b*N_ + n0 + j))*C1 + c0 + threadIdx.x] = tile[threadIdx.x][j];
}

// ---------------- xyz4 + new_xyz ----------------
__global__ void k_xyz(const float* __restrict__ xyz, float* __restrict__ out){
    int i = blockIdx.x*blockDim.x + threadIdx.x;
    if (i >= B_*N_) return;
    int b = i / N_, n = i % N_;
    float x = xyz[(b*3+0)*N_+n], y = xyz[(b*3+1)*N_+n], z = xyz[(b*3+2)*N_+n];
    d_xyz4[i] = make_float4(x, y, z, fmaf(z,z, fmaf(y,y, x*x)));
    if (n < S_){
        out[(b*3+0)*S_+n] = x;
        out[(b*3+1)*S_+n] = y;
        out[(b*3+2)*S_+n] = z;
    }
}

// ---------------- KNN: warp/query; 1024-cand tiles; batched ballots ----------------
__device__ __forceinline__ void knn_group(float d, int nbase, int lane,
                                          float& bd, int& bi, float& cm){
    unsigned m = __ballot_sync(FULLM, d < cm);
    if (m){
        do {
            int src = __ffs(m) - 1; m &= m - 1;
            float cd = __shfl_sync(FULLM, d, src);
            int   cn = nbase + src;
            float pk_ = __shfl_up_sync(FULLM, bd, 1);
            int   pi_ = __shfl_up_sync(FULLM, bi, 1);
            if (lane == 0) pk_ = -FINF;
            if (bd > cd){
                bool f = (pk_ <= cd);
                bd = f ? cd : pk_;
                bi = f ? cn : pi_;
            }
        } while (m);
        cm = __shfl_sync(FULLM, bd, 31);
    }
}

__global__ void __launch_bounds__(256) k_knn(){
    __shared__ float4 tile[1024];
    int t = threadIdx.x;
    int lane = t & 31, w = t >> 5;
    int qg = blockIdx.x*8 + w;
    int b = qg >> 12;
    int s = qg & (S_ - 1);
    const float4* base = &d_xyz4[b*N_];
    float4 c4 = base[s];
    float cx = c4.x, cy = c4.y, cz = c4.z, cs = c4.w;

    float bd = FINF;
    int   bi = 0;
    float cm = FINF;

    for (int j0 = 0; j0 < N_; j0 += 1024){
        #pragma unroll
        for (int i = 0; i < 4; i++)
            tile[t + 256*i] = base[j0 + t + 256*i];
        __syncthreads();
        if (j0 == 0){
            // first tile: per-group ballots while cm is loose
            for (int c = 0; c < 32; c++){
                float4 p = tile[c*32 + lane];
                float d = (cs + p.w) - 2.0f*fmaf(cz,p.z, fmaf(cy,p.y, cx*p.x));
                knn_group(d, j0 + c*32, lane, bd, bi, cm);
            }
        } else {
            // steady state: 1 ballot per 128 candidates on the no-hit path
            for (int c = 0; c < 32; c += 4){
                float4 p0 = tile[(c+0)*32 + lane];
                float4 p1 = tile[(c+1)*32 + lane];
                float4 p2 = tile[(c+2)*32 + lane];
                float4 p3 = tile[(c+3)*32 + lane];
                float d0 = (cs + p0.w) - 2.0f*fmaf(cz,p0.z, fmaf(cy,p0.y, cx*p0.x));
                float d1 = (cs + p1.w) - 2.0f*fmaf(cz,p1.z, fmaf(cy,p1.y, cx*p1.x));
                float d2 = (cs + p2.w) - 2.0f*fmaf(cz,p2.z, fmaf(cy,p2.y, cx*p2.x));
                float d3 = (cs + p3.w) - 2.0f*fmaf(cz,p3.z, fmaf(cy,p3.y, cx*p3.x));
                float dm = fminf(fminf(d0,d1), fminf(d2,d3));
                unsigned any = __ballot_sync(FULLM, dm < cm);
                if (any){
                    knn_group(d0, j0 + (c+0)*32, lane, bd, bi, cm);
                    knn_group(d1, j0 + (c+1)*32, lane, bd, bi, cm);
                    knn_group(d2, j0 + (c+2)*32, lane, bd, bi, cm);
                    knn_group(d3, j0 + (c+3)*32, lane, bd, bi, cm);
                }
            }
        }
        __syncthreads();
    }
    d_knn[qg*K_ + lane] = bi;
}

// ---------------- layer0: gather + GEMM, 8x8 tile per thread, warp per point ----------------
__global__ void __launch_bounds__(128, 4) k_g0(const float* __restrict__ W0g){
    extern __shared__ float dyn[];
    float* sx = dyn;                 // 4 * C0 * ST
    float* sw = dyn + 4*C0*ST;       // C0 * 64
    __shared__ float ssum[C1], ssq[C1];
    int t = threadIdx.x;
    int bs0 = blockIdx.x*4;

    for (int e = t; e < C0*64; e += 128){
        int ci = e >> 6, co = e & 63;
        sw[e] = W0g[co*C0 + ci];
    }
    if (t < C1){ ssum[t] = 0.f; ssq[t] = 0.f; }

    { // gather: 1 thread per (point, k)
        int s_l = t >> 5, k = t & 31;
        int bs = bs0 + s_l;
        int b = bs / S_, s = bs % S_;
        int idx = d_knn[bs*K_ + k];
        float* xr = &sx[s_l*C0*ST];
        float4 pc = d_xyz4[b*N_ + s];
        float4 pn = d_xyz4[b*N_ + idx];
        xr[0*ST + k] = pn.x - pc.x;
        xr[1*ST + k] = pn.y - pc.y;
        xr[2*ST + k] = pn.z - pc.z;
        const float4* prow = (const float4*)&d_pt[((size_t)(b*N_ + idx))*C1];
        #pragma unroll
        for (int q = 0; q < 16; q++){
            float4 v = prow[q];
            int c = 3 + q*4;
            xr[(c+0)*ST + k] = v.x;
            xr[(c+1)*ST + k] = v.y;
            xr[(c+2)*ST + k] = v.z;
            xr[(c+3)*ST + k] = v.w;
        }
    }
    __syncthreads();

    int lane = t & 31, wp = t >> 5;
    int kq = lane & 3, cog = lane >> 2;
    const float* xb_ = &sx[wp*C0*ST + kq*8];
    const float* wb_ = sw + cog*8;
    ull acc[8][4];
    #pragma unroll
    for (int j = 0; j < 8; j++){ acc[j][0]=0; acc[j][1]=0; acc[j][2]=0; acc[j][3]=0; }

    for (int ci = 0; ci < C0; ci++){
        float4 xa = *(const float4*)(xb_ + ci*ST);
        float4 xc = *(const float4*)(xb_ + ci*ST + 4);
        ull x0 = pk(xa.x,xa.y), x1 = pk(xa.z,xa.w);
        ull x2 = pk(xc.x,xc.y), x3 = pk(xc.z,xc.w);
        float4 wa = *(const float4*)(wb_ + ci*64);
        float4 wc = *(const float4*)(wb_ + ci*64 + 4);
        float wv[8] = {wa.x,wa.y,wa.z,wa.w, wc.x,wc.y,wc.z,wc.w};
        #pragma unroll
        for (int j = 0; j < 8; j++){
            ull w2 = pk(wv[j], wv[j]);
            acc[j][0] = fma2(w2, x0, acc[j][0]);
            acc[j][1] = fma2(w2, x1, acc[j][1]);
            acc[j][2] = fma2(w2, x2, acc[j][2]);
            acc[j][3] = fma2(w2, x3, acc[j][3]);
        }
    }

    int bs = bs0 + wp;
    float* orow = &d_buf0[(size_t)bs*C1*K_];
    float ls[8], lq[8];
    #pragma unroll
    for (int j = 0; j < 8; j++){
        float2 a0 = upk(acc[j][0]), a1 = upk(acc[j][1]);
        float2 a2 = upk(acc[j][2]), a3 = upk(acc[j][3]);
        *(float4*)&orow[(cog*8+j)*K_ + kq*8]     = make_float4(a0.x,a0.y,a1.x,a1.y);
        *(float4*)&orow[(cog*8+j)*K_ + kq*8 + 4] = make_float4(a2.x,a2.y,a3.x,a3.y);
        ls[j] = ((a0.x+a0.y)+(a1.x+a1.y)) + ((a2.x+a2.y)+(a3.x+a3.y));
        float q0 = fmaf(a0.x,a0.x, fmaf(a0.y,a0.y, fmaf(a1.x,a1.x, a1.y*a1.y)));
        lq[j] = fmaf(a2.x,a2.x, fmaf(a2.y,a2.y, fmaf(a3.x,a3.x, fmaf(a3.y,a3.y, q0))));
    }
    #pragma unroll
    for (int j = 0; j < 8; j++){
        ls[j] += __shfl_xor_sync(FULLM, ls[j], 1);
        ls[j] += __shfl_xor_sync(FULLM, ls[j], 2);
        lq[j] += __shfl_xor_sync(FULLM, lq[j], 1);
        lq[j] += __shfl_xor_sync(FULLM, lq[j], 2);
    }
    if (kq == 0){
        #pragma unroll
        for (int j = 0; j < 8; j++){
            atomicAdd(&ssum[cog*8+j], ls[j]);
            atomicAdd(&ssq [cog*8+j], lq[j]);
        }
    }
    __syncthreads();
    if (t < C1){
        d_ps0[blockIdx.x*C1 + t] = ssum[t];
        d_pq0[blockIdx.x*C1 + t] = ssq[t];
    }
}

// ---------------- stats finalize ----------------
__global__ void k_stats(int which){
    const float *ps, *pq; float *mean, *istd; int nblk, C;
    if (which == 0){ ps = d_ps0; pq = d_pq0; mean = d_mean0; istd = d_istd0; nblk = 2048; C = 64; }
    else if (which == 1){ ps = d_ps1; pq = d_pq1; mean = d_mean1; istd = d_istd1; nblk = 2048; C = 64; }
    else { ps = d_ps2; pq = d_pq2; mean = d_mean2; istd = d_istd2; nblk = 4096; C = 128; }
    int c = blockIdx.x;
    __shared__ float rs[256], rq[256];
    float s = 0.f, q = 0.f;
    for (int i = threadIdx.x; i < nblk; i += 256){ s += ps[i*C + c]; q += pq[i*C + c]; }
    rs[threadIdx.x] = s; rq[threadIdx.x] = q;
    __syncthreads();
    for (int o = 128; o; o >>= 1){
        if (threadIdx.x < o){ rs[threadIdx.x] += rs[threadIdx.x+o]; rq[threadIdx.x] += rq[threadIdx.x+o]; }
        __syncthreads();
    }
    if (threadIdx.x == 0){
        float cnt = (float)(B_*S_*K_);
        float m = rs[0] / cnt;
        float v = rq[0] / cnt - m*m;
        mean[c] = m;
        istd[c] = rsqrtf(v + 1e-5f);
    }
}

// ---------------- layer1 ----------------
__global__ void __launch_bounds__(128, 4) k_g1(const float* __restrict__ W1g,
                     const float* __restrict__ g0, const float* __restrict__ b0){
    extern __shared__ float dyn[];
    float* sx = dyn;                 // 4 * C1 * ST
    float* sw = dyn + 4*C1*ST;       // C1 * 64
    __shared__ float ssum[C2], ssq[C2], sa[C1], sb[C1];
    int t = threadIdx.x;
    int bs0 = blockIdx.x*4;

    for (int e = t; e < C1*64; e += 128){
        int ci = e >> 6, co = e & 63;
        sw[e] = W1g[co*C1 + ci];
    }
    if (t < C1){
        float a = d_istd0[t]*g0[t];
        sa[t] = a;
        sb[t] = fmaf(-d_mean0[t], a, b0[t]);
        ssum[t] = 0.f; ssq[t] = 0.f;
    }
    __syncthreads();

    {
        const float4* src = (const float4*)&d_buf0[(size_t)bs0*C1*K_];
        for (int e = t; e < 2048; e += 128){
            float4 v = src[e];
            int p = e >> 9, r2 = e & 511;
            int ci = r2 >> 3, k4 = (r2 & 7)*4;
            float a = sa[ci], bb = sb[ci], r;
            r = fmaf(v.x,a,bb); v.x = r >= 0.f ? r : 0.1f*r;
            r = fmaf(v.y,a,bb); v.y = r >= 0.f ? r : 0.1f*r;
            r = fmaf(v.z,a,bb); v.z = r >= 0.f ? r : 0.1f*r;
            r = fmaf(v.w,a,bb); v.w = r >= 0.f ? r : 0.1f*r;
            *(float4*)&sx[p*C1*ST + ci*ST + k4] = v;
        }
    }
    __syncthreads();

    int lane = t & 31, wp = t >> 5;
    int kq = lane & 3, cog = lane >> 2;
    const float* xb_ = &sx[wp*C1*ST + kq*8];
    const float* wb_ = sw + cog*8;
    ull acc[8][4];
    #pragma unroll
    for (int j = 0; j < 8; j++){ acc[j][0]=0; acc[j][1]=0; acc[j][2]=0; acc[j][3]=0; }

    for (int ci = 0; ci < C1; ci++){
        float4 xa = *(const float4*)(xb_ + ci*ST);
        float4 xc = *(const float4*)(xb_ + ci*ST + 4);
        ull x0 = pk(xa.x,xa.y), x1 = pk(xa.z,xa.w);
        ull x2 = pk(xc.x,xc.y), x3 = pk(xc.z,xc.w);
        float4 wa = *(const float4*)(wb_ + ci*64);
        float4 wc = *(const float4*)(wb_ + ci*64 + 4);
        float wv[8] = {wa.x,wa.y,wa.z,wa.w, wc.x,wc.y,wc.z,wc.w};
        #pragma unroll
        for (int j = 0; j < 8; j++){
            ull w2 = pk(wv[j], wv[j]);
            acc[j][0] = fma2(w2, x0, acc[j][0]);
            acc[j][1] = fma2(w2, x1, acc[j][1]);
            acc[j][2] = fma2(w2, x2, acc[j][2]);
            acc[j][3] = fma2(w2, x3, acc[j][3]);
        }
    }

    int bs = bs0 + wp;
    float* orow = &d_buf1[(size_t)bs*C2*K_];
    float ls[8], lq[8];
    #pragma unroll
    for (int j = 0; j < 8; j++){
        float2 a0 = upk(acc[j][0]), a1 = upk(acc[j][1]);
        float2 a2 = upk(acc[j][2]), a3 = upk(acc[j][3]);
        *(float4*)&orow[(cog*8+j)*K_ + kq*8]     = make_float4(a0.x,a0.y,a1.x,a1.y);
        *(float4*)&orow[(cog*8+j)*K_ + kq*8 + 4] = make_float4(a2.x,a2.y,a3.x,a3.y);
        ls[j] = ((a0.x+a0.y)+(a1.x+a1.y)) + ((a2.x+a2.y)+(a3.x+a3.y));
        float q0 = fmaf(a0.x,a0.x, fmaf(a0.y,a0.y, fmaf(a1.x,a1.x, a1.y*a1.y)));
        lq[j] = fmaf(a2.x,a2.x, fmaf(a2.y,a2.y, fmaf(a3.x,a3.x, fmaf(a3.y,a3.y, q0))));
    }
    #pragma unroll
    for (int j = 0; j < 8; j++){
        ls[j] += __shfl_xor_sync(FULLM, ls[j], 1);
        ls[j] += __shfl_xor_sync(FULLM, ls[j], 2);
        lq[j] += __shfl_xor_sync(FULLM, lq[j], 1);
        lq[j] += __shfl_xor_sync(FULLM, lq[j], 2);
    }
    if (kq == 0){
        #pragma unroll
        for (int j = 0; j < 8; j++){
            atomicAdd(&ssum[cog*8+j], ls[j]);
            atomicAdd(&ssq [cog*8+j], lq[j]);
        }
    }
    __syncthreads();
    if (t < C2){
        d_ps1[blockIdx.x*C2 + t] = ssum[t];
        d_pq1[blockIdx.x*C2 + t] = ssq[t];
    }
}

// ---------------- layer2: 2 points/block, 2 warps/point, max/min over k ----------------
__global__ void __launch_bounds__(128, 4) k_g2(const float* __restrict__ W2g,
                     const float* __restrict__ g1, const float* __restrict__ b1){
    extern __shared__ float dyn[];
    float* sx = dyn;                 // 2 * C2 * ST
    float* sw = dyn + 2*C2*ST;       // C2 * 128
    __shared__ float sa[C2], sb[C2], ssum[C3], ssq[C3];
    int t = threadIdx.x;
    int bs0 = blockIdx.x*2;

    for (int e = t; e < C2*C3; e += 128){
        int ci = e >> 7, co = e & 127;
        sw[e] = W2g[co*C2 + ci];
    }
    if (t < C2){
        float a = d_istd1[t]*g1[t];
        sa[t] = a;
        sb[t] = fmaf(-d_mean1[t], a, b1[t]);
    }
    if (t < C3){ ssum[t] = 0.f; ssq[t] = 0.f; }
    __syncthreads();

    {
        const float4* src = (const float4*)&d_buf1[(size_t)bs0*C2*K_];
        for (int e = t; e < 1024; e += 128){
            float4 v = src[e];
            int p = e >> 9, r2 = e & 511;
            int ci = r2 >> 3, k4 = (r2 & 7)*4;
            float a = sa[ci], bb = sb[ci], r;
            r = fmaf(v.x,a,bb); v.x = r >= 0.f ? r : 0.1f*r;
            r = fmaf(v.y,a,bb); v.y = r >= 0.f ? r : 0.1f*r;
            r = fmaf(v.z,a,bb); v.z = r >= 0.f ? r : 0.1f*r;
            r = fmaf(v.w,a,bb); v.w = r >= 0.f ? r : 0.1f*r;
            *(float4*)&sx[p*C2*ST + ci*ST + k4] = v;
        }
    }
    __syncthreads();

    int lane = t & 31, wp = t >> 5;
    int pt = wp >> 1, half = wp & 1;
    int kq = lane & 3, cog = lane >> 2;
    const float* xb_ = &sx[pt*C2*ST + kq*8];
    const float* wb_ = sw + half*64 + cog*8;
    ull acc[8][4];
    #pragma unroll
    for (int j = 0; j < 8; j++){ acc[j][0]=0; acc[j][1]=0; acc[j][2]=0; acc[j][3]=0; }

    for (int ci = 0; ci < C2; ci++){
        float4 xa = *(const float4*)(xb_ + ci*ST);
        float4 xc = *(const float4*)(xb_ + ci*ST + 4);
        ull x0 = pk(xa.x,xa.y), x1 = pk(xa.z,xa.w);
        ull x2 = pk(xc.x,xc.y), x3 = pk(xc.z,xc.w);
        float4 wa = *(const float4*)(wb_ + ci*128);
        float4 wc = *(const float4*)(wb_ + ci*128 + 4);
        float wv[8] = {wa.x,wa.y,wa.z,wa.w, wc.x,wc.y,wc.z,wc.w};
        #pragma unroll
        for (int j = 0; j < 8; j++){
            ull w2 = pk(wv[j], wv[j]);
            acc[j][0] = fma2(w2, x0, acc[j][0]);
            acc[j][1] = fma2(w2, x1, acc[j][1]);
            acc[j][2] = fma2(w2, x2, acc[j][2]);
            acc[j][3] = fma2(w2, x3, acc[j][3]);
        }
    }

    int bs = bs0 + pt;
    float lmx[8], lmn[8], ls[8], lq[8];
    #pragma unroll
    for (int j = 0; j < 8; j++){
        float2 a0 = upk(acc[j][0]), a1 = upk(acc[j][1]);
        float2 a2 = upk(acc[j][2]), a3 = upk(acc[j][3]);
        lmx[j] = fmaxf(fmaxf(fmaxf(a0.x,a0.y),fmaxf(a1.x,a1.y)),
                       fmaxf(fmaxf(a2.x,a2.y),fmaxf(a3.x,a3.y)));
        lmn[j] = fminf(fminf(fminf(a0.x,a0.y),fminf(a1.x,a1.y)),
                       fminf(fminf(a2.x,a2.y),fminf(a3.x,a3.y)));
        ls[j] = ((a0.x+a0.y)+(a1.x+a1.y)) + ((a2.x+a2.y)+(a3.x+a3.y));
        float q0 = fmaf(a0.x,a0.x, fmaf(a0.y,a0.y, fmaf(a1.x,a1.x, a1.y*a1.y)));
        lq[j] = fmaf(a2.x,a2.x, fmaf(a2.y,a2.y, fmaf(a3.x,a3.x, fmaf(a3.y,a3.y, q0))));
    }
    #pragma unroll
    for (int j = 0; j < 8; j++){
        lmx[j] = fmaxf(lmx[j], __shfl_xor_sync(FULLM, lmx[j], 1));
        lmx[j] = fmaxf(lmx[j], __shfl_xor_sync(FULLM, lmx[j], 2));
        lmn[j] = fminf(lmn[j], __shfl_xor_sync(FULLM, lmn[j], 1));
        lmn[j] = fminf(lmn[j], __shfl_xor_sync(FULLM, lmn[j], 2));
        ls[j] += __shfl_xor_sync(FULLM, ls[j], 1);
        ls[j] += __shfl_xor_sync(FULLM, ls[j], 2);
        lq[j] += __shfl_xor_sync(FULLM, lq[j], 1);
        lq[j] += __shfl_xor_sync(FULLM, lq[j], 2);
    }
    if (kq == 0){
        #pragma unroll
        for (int j = 0; j < 8; j++){
            int co = half*64 + cog*8 + j;
            d_maxb[bs*C3 + co] = lmx[j];
            d_minb[bs*C3 + co] = lmn[j];
            atomicAdd(&ssum[co], ls[j]);
            atomicAdd(&ssq [co], lq[j]);
        }
    }
    __syncthreads();
    if (t < C3){
        d_ps2[blockIdx.x*C3 + t] = ssum[t];
        d_pq2[blockIdx.x*C3 + t] = ssq[t];
    }
}

// ---------------- final ----------------
__global__ void k_final(const float* __restrict__ g2, const float* __restrict__ b2,
                        float* __restrict__ out){
    int o = blockIdx.x*blockDim.x + threadIdx.x;
    if (o >= B_*C3*S_) return;
    int s  = o & (S_ - 1);
    int co = (o >> 12) & 127;
    int b  = o >> 19;
    float a = d_istd2[co]*g2[co];
    float base = fmaf(-d_mean2[co], a, b2[co]);
    int bs = b*S_ + s;
    float yv = (a > 0.f) ? d_maxb[bs*C3 + co] : ((a < 0.f) ? d_minb[bs*C3 + co] : 0.f);
    float r = fmaf(yv, a, base);
    out[B_*3*S_ + o] = r >= 0.f ? r : 0.1f*r;
}

extern "C" void kernel_launch(void* const* d_in, const int* in_sizes, int n_in,
                              void* d_out, int out_size){
    const float* xyz    = (const float*)d_in[0];
    const float* points = (const float*)d_in[1];
    const float* W0     = (const float*)d_in[2];
    const float* W1     = (const float*)d_in[3];
    const float* W2     = (const float*)d_in[4];
    const float* g0     = (const float*)d_in[5];
    const float* b0     = (const float*)d_in[6];
    const float* g1     = (const float*)d_in[7];
    const float* b1     = (const float*)d_in[8];
    const float* g2     = (const float*)d_in[9];
    const float* b2     = (const float*)d_in[10];
    float* out = (float*)d_out;

    const int smem0 = (4*C0*ST + C0*64) * 4;
    const int smem1 = (4*C1*ST + C1*64) * 4;
    const int smem2 = (2*C2*ST + C2*C3) * 4;
    cudaFuncSetAttribute(k_g0, cudaFuncAttributeMaxDynamicSharedMemorySize, smem0);
    cudaFuncSetAttribute(k_g1, cudaFuncAttributeMaxDynamicSharedMemorySize, smem1);
    cudaFuncSetAttribute(k_g2, cudaFuncAttributeMaxDynamicSharedMemorySize, smem2);

    k_tr  <<<dim3(N_/32, C1/32, B_), dim3(32,8)>>>(points);
    k_xyz <<<(B_*N_ + 255)/256, 256>>>(xyz, out);
    k_knn <<<B_*S_/8, 256>>>();
    k_g0  <<<B_*S_/4, 128, smem0>>>(W0);
    k_stats<<<64, 256>>>(0);
    k_g1  <<<B_*S_/4, 128, smem1>>>(W1, g0, b0);
    k_stats<<<64, 256>>>(1);
    k_g2  <<<B_*S_/2, 128, smem2>>>(W2, g1, b1);
    k_stats<<<128, 256>>>(2);
    k_final<<<(B_*C3*S_ + 255)/256, 256>>>(g2, b2, out);
}